// round 15
// baseline (speedup 1.0000x reference)
#include <cuda_runtime.h>
#include <math.h>

static constexpr int NN = 100000;   // nodes (capacity)
static constexpr int EE = 1600000;  // edges (capacity)
static constexpr int DD = 64;
static constexpr int ROWS_PB = 32;  // rows per block in k_out

// Scratch (static device globals; no allocation anywhere).
// Per-launch invariants: k_node zeroes z / sf / st at the start of every
// launch (BSS zero makes the first run correct); g_Mi max is idempotent.
__device__ __align__(16) float  g_z[(size_t)NN * DD];  // 25.6 MB z accumulator
__device__ float  g_as[NN], g_ad[NN];                  // per-node logit halves
__device__ float  g_norm[NN];                          // ||tax_n||
__device__ int    g_Mi;                                // max norm (float bits; pos -> int cmp ok)
__device__ float  g_sf[NN], g_st[NN];                  // softmax denominators
__device__ __align__(8) float2 g_e2[EE];               // (e_f, e_t), original edge order

// ---------------------------------------------------------------------------
// K1: zero z + denominators, per-node dots a_s = h.wh[0:64], a_d = h.wh[64:],
//     ||tax||, block-reduced global max norm (1 atomic per block)
__global__ void k_node(const float* __restrict__ h, const float* __restrict__ tax,
                       const float* __restrict__ wh, int n) {
    __shared__ float smax[8];
    int gt = blockIdx.x * blockDim.x + threadIdx.x;
    int w = gt >> 5, lane = gt & 31;
    if (gt < n * (DD / 4))
        reinterpret_cast<float4*>(g_z)[gt] = make_float4(0.f, 0.f, 0.f, 0.f);
    if (gt < n) { g_sf[gt] = 0.f; g_st[gt] = 0.f; }
    float nr = 0.f;
    if (w < n) {
        float2 hv = *reinterpret_cast<const float2*>(h + (size_t)w * DD + lane * 2);
        float2 tv = *reinterpret_cast<const float2*>(tax + (size_t)w * DD + lane * 2);
        float2 wa = *reinterpret_cast<const float2*>(wh + lane * 2);
        float2 wb = *reinterpret_cast<const float2*>(wh + DD + lane * 2);
        float ps = hv.x * wa.x + hv.y * wa.y;
        float pd = hv.x * wb.x + hv.y * wb.y;
        float nq = tv.x * tv.x + tv.y * tv.y;
#pragma unroll
        for (int o = 16; o; o >>= 1) {
            ps += __shfl_xor_sync(0xffffffffu, ps, o);
            pd += __shfl_xor_sync(0xffffffffu, pd, o);
            nq += __shfl_xor_sync(0xffffffffu, nq, o);
        }
        if (lane == 0) {
            g_as[w] = ps;
            g_ad[w] = pd;
            nr = sqrtf(nq);
            g_norm[w] = nr;
        }
    }
    float wm = nr;
#pragma unroll
    for (int o = 16; o; o >>= 1) wm = fmaxf(wm, __shfl_xor_sync(0xffffffffu, wm, o));
    if (lane == 0) smax[threadIdx.x >> 5] = wm;
    __syncthreads();
    if (threadIdx.x == 0) {
        float m = smax[0];
#pragma unroll
        for (int i = 1; i < 8; i++) m = fmaxf(m, smax[i]);
        if (m > 0.f) atomicMax(&g_Mi, __float_as_int(m));   // idempotent across replays
    }
}

// K2: fused edge pass, all fp32. Per-dst shift S_d = ||tax_d||*M - 80
// (d-only -> cancels in softmax; Cauchy-Schwarz bounds p-S_d in [-~64, 80]).
__global__ void k_edge(const float* __restrict__ tax, const int* __restrict__ src,
                       const int* __restrict__ dst, int e) {
    int gt = blockIdx.x * blockDim.x + threadIdx.x;
    int w = gt >> 3, l = gt & 7;
    if (w >= e) return;
    int s = src[w], d = dst[w];
    const float4* ts = reinterpret_cast<const float4*>(tax + (size_t)s * DD);
    const float4* td = reinterpret_cast<const float4*>(tax + (size_t)d * DD);
    float4 a0 = ts[l * 2],     b0 = td[l * 2];
    float4 a1 = ts[l * 2 + 1], b1 = td[l * 2 + 1];
    float p = a0.x * b0.x + a0.y * b0.y + a0.z * b0.z + a0.w * b0.w
            + a1.x * b1.x + a1.y * b1.y + a1.z * b1.z + a1.w * b1.w;
#pragma unroll
    for (int o = 4; o; o >>= 1) p += __shfl_xor_sync(0xffffffffu, p, o);
    if (l == 0) {
        float x = g_as[s] + g_ad[d];
        float wf = x >= 0.f ? x : 0.01f * x;      // leaky_relu(0.01); |wf| small
        float M = __int_as_float(g_Mi);
        float shift = g_norm[d] * M - 80.f;
        float ef = __expf(wf);
        float et = __expf(p - shift);
        atomicAdd(&g_sf[d], ef);
        atomicAdd(&g_st[d], et);
        g_e2[w] = make_float2(ef, et);
    }
}

// K3: edge-parallel scatter. 16 threads/edge, zero serial chains:
// alpha from denominators + h row gather + red.global.add.v4.
__global__ void k_scat(const float* __restrict__ h, const int* __restrict__ src,
                       const int* __restrict__ dst, int e) {
    int gt = blockIdx.x * blockDim.x + threadIdx.x;
    int w = gt >> 4, l = gt & 15;
    if (w >= e) return;
    int s = src[w], d = dst[w];
    float2 ev = g_e2[w];
    float a = ev.x * (0.5f / g_sf[d]) + ev.y * (0.5f / g_st[d]);
    float4 hv = *reinterpret_cast<const float4*>(h + (size_t)s * DD + l * 4);
    float* zp = g_z + (size_t)d * DD + l * 4;
    asm volatile("red.global.add.v4.f32 [%0], {%1, %2, %3, %4};"
                 :: "l"(zp), "f"(a * hv.x), "f"(a * hv.y), "f"(a * hv.z), "f"(a * hv.w)
                 : "memory");
}

// K4 (PROFILED SLOT): out = z @ W^T + b.
// W row-major in smem (68-float padded rows: LDS.128 by lane c hits banks
// (4c+k)%32, conflict-free). Each thread hoists its whole W row c into 64
// registers (16x LDS.128 once), then per z-row: 16 warp-uniform LDG.128
// (broadcast) + 64 reg-FFMA. 32 rows/block amortizes the W load 8x.
__global__ void __launch_bounds__(256) k_out(const float* __restrict__ Ww,
                                             const float* __restrict__ Wb,
                                             float* __restrict__ out, int n) {
    __shared__ float Ws[DD * (DD + 4)];   // row c at c*68 (272B: 16B-aligned)
    __shared__ float bs[DD];
    int tid = threadIdx.y * 64 + threadIdx.x;
    for (int i = tid; i < DD * DD; i += 256) {
        int c = i >> 6, k = i & 63;
        Ws[c * 68 + k] = Ww[i];           // consecutive k -> consecutive banks
    }
    if (tid < DD) bs[tid] = Wb[tid];
    __syncthreads();
    int c = threadIdx.x;
    // hoist W row c into registers (16 x LDS.128, conflict-free phases)
    float wreg[DD];
#pragma unroll
    for (int k4 = 0; k4 < 16; k4++) {
        float4 wv = *reinterpret_cast<const float4*>(&Ws[c * 68 + k4 * 4]);
        wreg[k4 * 4 + 0] = wv.x;
        wreg[k4 * 4 + 1] = wv.y;
        wreg[k4 * 4 + 2] = wv.z;
        wreg[k4 * 4 + 3] = wv.w;
    }
    float bias = bs[c];
#pragma unroll
    for (int r = 0; r < ROWS_PB / 4; r++) {
        int row = blockIdx.x * ROWS_PB + r * 4 + threadIdx.y;
        if (row < n) {
            const float4* zr = reinterpret_cast<const float4*>(g_z + (size_t)row * DD);
            float acc = bias;
#pragma unroll
            for (int k4 = 0; k4 < 16; k4++) {
                float4 zv = zr[k4];                      // warp-uniform broadcast
                acc += zv.x * wreg[k4 * 4 + 0];
                acc += zv.y * wreg[k4 * 4 + 1];
                acc += zv.z * wreg[k4 * 4 + 2];
                acc += zv.w * wreg[k4 * 4 + 3];
            }
            out[(size_t)row * DD + c] = acc;
        }
    }
}

// ---------------------------------------------------------------------------
extern "C" void kernel_launch(void* const* d_in, const int* in_sizes, int n_in,
                              void* d_out, int out_size) {
    const float* h   = (const float*)d_in[0];
    const float* tax = (const float*)d_in[1];
    const int*   src = (const int*)d_in[2];
    const int*   dst = (const int*)d_in[3];
    const float* wh  = (const float*)d_in[4];
    const float* Ww  = (const float*)d_in[5];
    const float* Wb  = (const float*)d_in[6];
    float* out = (float*)d_out;

    int n = in_sizes[0] / DD;
    int e = in_sizes[2];

    k_node<<<(int)(((long long)n * 32 + 255) / 256), 256>>>(h, tax, wh, n);        // 1
    k_edge<<<(int)(((long long)e * 8 + 255) / 256), 256>>>(tax, src, dst, e);      // 2
    k_scat<<<(int)(((long long)e * 16 + 255) / 256), 256>>>(h, src, dst, e);       // 3
    k_out<<<(n + ROWS_PB - 1) / ROWS_PB, dim3(64, 4)>>>(Ww, Wb, out, n);           // 4 <- profiled
}

// round 16
// speedup vs baseline: 1.0638x; 1.0638x over previous
#include <cuda_runtime.h>
#include <math.h>

static constexpr int NN = 100000;   // nodes (capacity)
static constexpr int EE = 1600000;  // edges (capacity)
static constexpr int DD = 64;
static constexpr int ROWS_PB = 16;  // rows per block in k_out

// Scratch (static device globals; no allocation anywhere).
// Per-launch invariants: k_node zeroes z / sf / st at the start of every
// launch (BSS zero makes the first run correct); g_Mi max is idempotent.
__device__ __align__(16) float  g_z[(size_t)NN * DD];  // 25.6 MB z accumulator
__device__ float  g_as[NN], g_ad[NN];                  // per-node logit halves
__device__ float  g_norm[NN];                          // ||tax_n||
__device__ int    g_Mi;                                // max norm (float bits; pos -> int cmp ok)
__device__ float  g_sf[NN], g_st[NN];                  // softmax denominators
__device__ __align__(8) float2 g_e2[EE];               // (e_f, e_t), original edge order

// ---------------------------------------------------------------------------
// K1: zero z + denominators, per-node dots a_s = h.wh[0:64], a_d = h.wh[64:],
//     ||tax||, block-reduced global max norm (1 atomic per block)
__global__ void k_node(const float* __restrict__ h, const float* __restrict__ tax,
                       const float* __restrict__ wh, int n) {
    __shared__ float smax[8];
    int gt = blockIdx.x * blockDim.x + threadIdx.x;
    int w = gt >> 5, lane = gt & 31;
    if (gt < n * (DD / 4))
        reinterpret_cast<float4*>(g_z)[gt] = make_float4(0.f, 0.f, 0.f, 0.f);
    if (gt < n) { g_sf[gt] = 0.f; g_st[gt] = 0.f; }
    float nr = 0.f;
    if (w < n) {
        float2 hv = *reinterpret_cast<const float2*>(h + (size_t)w * DD + lane * 2);
        float2 tv = *reinterpret_cast<const float2*>(tax + (size_t)w * DD + lane * 2);
        float2 wa = *reinterpret_cast<const float2*>(wh + lane * 2);
        float2 wb = *reinterpret_cast<const float2*>(wh + DD + lane * 2);
        float ps = hv.x * wa.x + hv.y * wa.y;
        float pd = hv.x * wb.x + hv.y * wb.y;
        float nq = tv.x * tv.x + tv.y * tv.y;
#pragma unroll
        for (int o = 16; o; o >>= 1) {
            ps += __shfl_xor_sync(0xffffffffu, ps, o);
            pd += __shfl_xor_sync(0xffffffffu, pd, o);
            nq += __shfl_xor_sync(0xffffffffu, nq, o);
        }
        if (lane == 0) {
            g_as[w] = ps;
            g_ad[w] = pd;
            nr = sqrtf(nq);
            g_norm[w] = nr;
        }
    }
    float wm = nr;
#pragma unroll
    for (int o = 16; o; o >>= 1) wm = fmaxf(wm, __shfl_xor_sync(0xffffffffu, wm, o));
    if (lane == 0) smax[threadIdx.x >> 5] = wm;
    __syncthreads();
    if (threadIdx.x == 0) {
        float m = smax[0];
#pragma unroll
        for (int i = 1; i < 8; i++) m = fmaxf(m, smax[i]);
        if (m > 0.f) atomicMax(&g_Mi, __float_as_int(m));   // idempotent across replays
    }
}

// K2: fused edge pass, all fp32. Per-dst shift S_d = ||tax_d||*M - 80
// (d-only -> cancels in softmax; Cauchy-Schwarz bounds p-S_d in [-~64, 80]).
__global__ void k_edge(const float* __restrict__ tax, const int* __restrict__ src,
                       const int* __restrict__ dst, int e) {
    int gt = blockIdx.x * blockDim.x + threadIdx.x;
    int w = gt >> 3, l = gt & 7;
    if (w >= e) return;
    int s = src[w], d = dst[w];
    const float4* ts = reinterpret_cast<const float4*>(tax + (size_t)s * DD);
    const float4* td = reinterpret_cast<const float4*>(tax + (size_t)d * DD);
    float4 a0 = ts[l * 2],     b0 = td[l * 2];
    float4 a1 = ts[l * 2 + 1], b1 = td[l * 2 + 1];
    float p = a0.x * b0.x + a0.y * b0.y + a0.z * b0.z + a0.w * b0.w
            + a1.x * b1.x + a1.y * b1.y + a1.z * b1.z + a1.w * b1.w;
#pragma unroll
    for (int o = 4; o; o >>= 1) p += __shfl_xor_sync(0xffffffffu, p, o);
    if (l == 0) {
        float x = g_as[s] + g_ad[d];
        float wf = x >= 0.f ? x : 0.01f * x;      // leaky_relu(0.01); |wf| small
        float M = __int_as_float(g_Mi);
        float shift = g_norm[d] * M - 80.f;
        float ef = __expf(wf);
        float et = __expf(p - shift);
        atomicAdd(&g_sf[d], ef);
        atomicAdd(&g_st[d], et);
        g_e2[w] = make_float2(ef, et);
    }
}

// K3: edge-parallel scatter. 16 threads/edge, zero serial chains:
// alpha from denominators + h row gather + red.global.add.v4.
__global__ void k_scat(const float* __restrict__ h, const int* __restrict__ src,
                       const int* __restrict__ dst, int e) {
    int gt = blockIdx.x * blockDim.x + threadIdx.x;
    int w = gt >> 4, l = gt & 15;
    if (w >= e) return;
    int s = src[w], d = dst[w];
    float2 ev = g_e2[w];
    float a = ev.x * (0.5f / g_sf[d]) + ev.y * (0.5f / g_st[d]);
    float4 hv = *reinterpret_cast<const float4*>(h + (size_t)s * DD + l * 4);
    float* zp = g_z + (size_t)d * DD + l * 4;
    asm volatile("red.global.add.v4.f32 [%0], {%1, %2, %3, %4};"
                 :: "l"(zp), "f"(a * hv.x), "f"(a * hv.y), "f"(a * hv.z), "f"(a * hv.w)
                 : "memory");
}

// K4 (PROFILED SLOT): out = z @ W^T + b.
// W row-major in smem, 68-float row stride: LDS.128 by lane c hits banks
// (4c+4k4..+3) -> each 8-lane phase covers all 32 banks, conflict-free.
// Per row: 16 LDS.128 + 16 warp-uniform LDG.128 + 64 FFMA; no register
// hoist (keeps regs ~40 -> high occupancy, unlike the 130-reg variant).
__global__ void __launch_bounds__(256) k_out(const float* __restrict__ Ww,
                                             const float* __restrict__ Wb,
                                             float* __restrict__ out, int n) {
    __shared__ float Ws[DD * (DD + 4)];   // row c at c*68 (272B: 16B-aligned)
    __shared__ float bs[DD];
    int tid = threadIdx.y * 64 + threadIdx.x;
    for (int i = tid; i < DD * DD; i += 256) {
        int c = i >> 6, k = i & 63;
        Ws[c * 68 + k] = Ww[i];           // consecutive k -> consecutive banks
    }
    if (tid < DD) bs[tid] = Wb[tid];
    __syncthreads();
    int c = threadIdx.x;
    const float4* wrow = reinterpret_cast<const float4*>(&Ws[c * 68]);
    float bias = bs[c];
#pragma unroll
    for (int r = 0; r < ROWS_PB / 4; r++) {
        int row = blockIdx.x * ROWS_PB + r * 4 + threadIdx.y;
        if (row < n) {
            const float4* zr = reinterpret_cast<const float4*>(g_z + (size_t)row * DD);
            float acc = bias;
#pragma unroll
            for (int k4 = 0; k4 < 16; k4++) {
                float4 zv = zr[k4];        // warp-uniform broadcast (1 sector)
                float4 wv = wrow[k4];      // LDS.128, conflict-free
                acc += zv.x * wv.x;
                acc += zv.y * wv.y;
                acc += zv.z * wv.z;
                acc += zv.w * wv.w;
            }
            out[(size_t)row * DD + c] = acc;
        }
    }
}

// ---------------------------------------------------------------------------
extern "C" void kernel_launch(void* const* d_in, const int* in_sizes, int n_in,
                              void* d_out, int out_size) {
    const float* h   = (const float*)d_in[0];
    const float* tax = (const float*)d_in[1];
    const int*   src = (const int*)d_in[2];
    const int*   dst = (const int*)d_in[3];
    const float* wh  = (const float*)d_in[4];
    const float* Ww  = (const float*)d_in[5];
    const float* Wb  = (const float*)d_in[6];
    float* out = (float*)d_out;

    int n = in_sizes[0] / DD;
    int e = in_sizes[2];

    k_node<<<(int)(((long long)n * 32 + 255) / 256), 256>>>(h, tax, wh, n);        // 1
    k_edge<<<(int)(((long long)e * 8 + 255) / 256), 256>>>(tax, src, dst, e);      // 2
    k_scat<<<(int)(((long long)e * 16 + 255) / 256), 256>>>(h, src, dst, e);       // 3
    k_out<<<(n + ROWS_PB - 1) / ROWS_PB, dim3(64, 4)>>>(Ww, Wb, out, n);           // 4 <- profiled
}